// round 2
// baseline (speedup 1.0000x reference)
#include <cuda_runtime.h>
#include <cstdint>

#define HID   2048
#define INTER 8192
#define RANK  16
#define SEQ   2048
#define NB    4
#define MTOT  8192          // NB*SEQ rows
#define KSEL  10

// ---------------- scratch (static device globals; no allocation) -------------
__device__ float g_x2[(size_t)MTOT * INTER];   // 256 MB relu(up) activations
__device__ float g_tup[MTOT * RANK];
__device__ float g_tdown[MTOT * RANK];
__device__ int   g_zero[NB * INTER];
__device__ int   g_topk[NB * KSEL];

// ---------------- helpers ----------------------------------------------------
__global__ void zinit_kernel() {
    int i = blockIdx.x * blockDim.x + threadIdx.x;
    if (i < NB * INTER) g_zero[i] = 0;
}

// T[M,16] = X[M,K] @ A[K,16]   (32 rows / block, 256 threads)
__global__ __launch_bounds__(256) void gemm_rank16(
    const float* __restrict__ X, const float* __restrict__ A,
    float* __restrict__ T, int K)
{
    __shared__ float xs[32][64];
    __shared__ float as[64][16];
    const int tid = threadIdx.x;
    const int bm  = blockIdx.x * 32;
    const int r0  = tid >> 4;        // 0..15
    const int r1  = r0 + 16;         // 16..31
    const int col = tid & 15;
    float acc0 = 0.f, acc1 = 0.f;

    for (int k0 = 0; k0 < K; k0 += 64) {
        __syncthreads();
#pragma unroll
        for (int r = 0; r < 2; r++) {
            int i4  = tid * 2 + r;               // 0..511 float4s of the 32x64 tile
            int row = i4 >> 4;
            int c   = (i4 & 15) * 4;
            *(float4*)&xs[row][c] =
                *(const float4*)(X + (size_t)(bm + row) * K + k0 + c);
        }
        {
            int row = tid >> 2;                  // 64x16 tile: 256 float4s
            int c   = (tid & 3) * 4;
            *(float4*)&as[row][c] =
                *(const float4*)(A + (size_t)(k0 + row) * RANK + c);
        }
        __syncthreads();
#pragma unroll 16
        for (int kk = 0; kk < 64; kk++) {
            float w = as[kk][col];
            acc0 = fmaf(xs[r0][kk], w, acc0);
            acc1 = fmaf(xs[r1][kk], w, acc1);
        }
    }
    T[(bm + r0) * RANK + col] = acc0;
    T[(bm + r1) * RANK + col] = acc1;
}

// C[M,N] = A[M,K] @ W[K,N] + loraT[M,16] @ loraB[16,N]
// RELU_COUNT: apply relu, accumulate per-(batch,channel) zero counts.
// Tiles: 128x128x16, 256 threads, 8x8 per thread.
template <bool RELU_COUNT>
__global__ __launch_bounds__(256) void gemm_lora(
    const float* __restrict__ A, const float* __restrict__ W,
    const float* __restrict__ loraT, const float* __restrict__ loraB,
    float* __restrict__ C, int N, int K)
{
    __shared__ float As[16][128];
    __shared__ float Ws[16][128];
    __shared__ float Ts[128][16];
    __shared__ float Bsh[16][128];
    __shared__ int   zc[128];

    const int tid = threadIdx.x;
    const int bm  = blockIdx.y * 128;
    const int bn  = blockIdx.x * 128;

    // preload LoRA tiles (each 2048 floats = 512 float4, 2 per thread)
#pragma unroll
    for (int r = 0; r < 2; r++) {
        int i4 = tid * 2 + r;
        int trow = i4 >> 2, tc = (i4 & 3) * 4;
        float4 v = *(const float4*)(loraT + (size_t)(bm + trow) * RANK + tc);
        Ts[trow][tc]   = v.x; Ts[trow][tc+1] = v.y;
        Ts[trow][tc+2] = v.z; Ts[trow][tc+3] = v.w;
        int br = i4 >> 5, bc = (i4 & 31) * 4;
        *(float4*)&Bsh[br][bc] = *(const float4*)(loraB + (size_t)br * N + bn + bc);
    }

    float acc[8][8];
#pragma unroll
    for (int i = 0; i < 8; i++)
#pragma unroll
        for (int j = 0; j < 8; j++) acc[i][j] = 0.f;

    const int rowb = (tid >> 4) * 8;
    const int colb = (tid & 15) * 8;

    for (int k0 = 0; k0 < K; k0 += 16) {
        __syncthreads();
#pragma unroll
        for (int r = 0; r < 2; r++) {
            int i4 = tid * 2 + r;
            int arow = i4 >> 2, ak = (i4 & 3) * 4;
            float4 v = *(const float4*)(A + (size_t)(bm + arow) * K + k0 + ak);
            As[ak][arow]   = v.x; As[ak+1][arow] = v.y;
            As[ak+2][arow] = v.z; As[ak+3][arow] = v.w;
            int wr = i4 >> 5, wc = (i4 & 31) * 4;
            *(float4*)&Ws[wr][wc] = *(const float4*)(W + (size_t)(k0 + wr) * N + bn + wc);
        }
        __syncthreads();
#pragma unroll
        for (int kk = 0; kk < 16; kk++) {
            float ra[8], rw[8];
#pragma unroll
            for (int i = 0; i < 8; i++) ra[i] = As[kk][rowb + i];
#pragma unroll
            for (int j = 0; j < 8; j++) rw[j] = Ws[kk][colb + j];
#pragma unroll
            for (int i = 0; i < 8; i++)
#pragma unroll
                for (int j = 0; j < 8; j++)
                    acc[i][j] = fmaf(ra[i], rw[j], acc[i][j]);
        }
    }

    // rank-16 LoRA epilogue
#pragma unroll
    for (int r = 0; r < RANK; r++) {
        float ta[8], bb[8];
#pragma unroll
        for (int i = 0; i < 8; i++) ta[i] = Ts[rowb + i][r];
#pragma unroll
        for (int j = 0; j < 8; j++) bb[j] = Bsh[r][colb + j];
#pragma unroll
        for (int i = 0; i < 8; i++)
#pragma unroll
            for (int j = 0; j < 8; j++)
                acc[i][j] = fmaf(ta[i], bb[j], acc[i][j]);
    }

    if (RELU_COUNT) {
        __syncthreads();
        if (tid < 128) zc[tid] = 0;
        __syncthreads();
        int cnt[8];
#pragma unroll
        for (int j = 0; j < 8; j++) cnt[j] = 0;
#pragma unroll
        for (int i = 0; i < 8; i++) {
#pragma unroll
            for (int j = 0; j < 8; j++) {
                float v = fmaxf(acc[i][j], 0.0f);
                acc[i][j] = v;
                cnt[j] += (v == 0.0f);
            }
            float* cp = C + (size_t)(bm + rowb + i) * N + bn + colb;
            *(float4*)cp       = make_float4(acc[i][0], acc[i][1], acc[i][2], acc[i][3]);
            *(float4*)(cp + 4) = make_float4(acc[i][4], acc[i][5], acc[i][6], acc[i][7]);
        }
#pragma unroll
        for (int j = 0; j < 8; j++) atomicAdd(&zc[colb + j], cnt[j]);
        __syncthreads();
        if (tid < 128) {
            int b = bm / SEQ;                       // 128-row tiles never straddle batches
            atomicAdd(&g_zero[b * INTER + bn + tid], zc[tid]);
        }
    } else {
#pragma unroll
        for (int i = 0; i < 8; i++) {
            float* cp = C + (size_t)(bm + rowb + i) * N + bn + colb;
            *(float4*)cp       = make_float4(acc[i][0], acc[i][1], acc[i][2], acc[i][3]);
            *(float4*)(cp + 4) = make_float4(acc[i][4], acc[i][5], acc[i][6], acc[i][7]);
        }
    }
}

// per-batch selection of KSEL channels with fewest zeros; jax.lax.top_k order:
// ascending zero-count, ties broken by lower channel index.
__global__ void topk_kernel() {
    const int b   = blockIdx.x;
    const int tid = threadIdx.x;
    __shared__ unsigned red[256];
    __shared__ int chosen[KSEL];

    for (int sel = 0; sel < KSEL; sel++) {
        unsigned best = 0xFFFFFFFFu;
        for (int j = tid; j < INTER; j += 256) {
            bool skip = false;
            for (int c = 0; c < sel; c++)
                if (chosen[c] == j) skip = true;
            if (!skip) {
                unsigned key = ((unsigned)g_zero[b * INTER + j] << 13) | (unsigned)j;
                best = min(best, key);
            }
        }
        red[tid] = best;
        __syncthreads();
        for (int s = 128; s > 0; s >>= 1) {
            if (tid < s) red[tid] = min(red[tid], red[tid + s]);
            __syncthreads();
        }
        if (tid == 0) {
            chosen[sel] = (int)(red[0] & 8191u);
            g_topk[b * KSEL + sel] = chosen[sel];
        }
        __syncthreads();
    }
}

__global__ void gather_kernel(float* __restrict__ out) {
    int idx = blockIdx.x * blockDim.x + threadIdx.x;   // [0, NB*SEQ*KSEL)
    if (idx >= NB * SEQ * KSEL) return;
    int i   = idx % KSEL;
    int row = idx / KSEL;                              // global token row
    int b   = row / SEQ;
    out[idx] = g_x2[(size_t)row * INTER + g_topk[b * KSEL + i]];
}

// ---------------- launch ------------------------------------------------------
extern "C" void kernel_launch(void* const* d_in, const int* in_sizes, int n_in,
                              void* d_out, int out_size)
{
    const float* x1        = (const float*)d_in[0];
    const float* w_up      = (const float*)d_in[1];
    const float* w_up_la   = (const float*)d_in[2];
    const float* w_up_lb   = (const float*)d_in[3];
    const float* w_down    = (const float*)d_in[4];
    const float* w_down_la = (const float*)d_in[5];
    const float* w_down_lb = (const float*)d_in[6];
    float* out = (float*)d_out;

    float *px2, *ptup, *ptdown;
    cudaGetSymbolAddress((void**)&px2,    g_x2);
    cudaGetSymbolAddress((void**)&ptup,   g_tup);
    cudaGetSymbolAddress((void**)&ptdown, g_tdown);

    zinit_kernel<<<(NB * INTER + 1023) / 1024, 1024>>>();

    // t_up = x1 @ w_up_lora_a
    gemm_rank16<<<MTOT / 32, 256>>>(x1, w_up_la, ptup, HID);

    // x2 = relu(x1 @ w_up + t_up @ w_up_lora_b), plus per-channel zero counts
    gemm_lora<true><<<dim3(INTER / 128, MTOT / 128), 256>>>(
        x1, w_up, ptup, w_up_lb, px2, INTER, HID);

    // t_down = x2 @ w_down_lora_a
    gemm_rank16<<<MTOT / 32, 256>>>(px2, w_down_la, ptdown, INTER);

    // y2 = x2 @ w_down + t_down @ w_down_lora_b  -> first output
    gemm_lora<false><<<dim3(HID / 128, MTOT / 128), 256>>>(
        px2, w_down, ptdown, w_down_lb, out, HID, INTER);

    // top-10 channels per batch, then gather -> second output
    topk_kernel<<<NB, 256>>>();
    gather_kernel<<<(NB * SEQ * KSEL + 255) / 256, 256>>>(out + (size_t)MTOT * HID);
}

// round 3
// speedup vs baseline: 1.0007x; 1.0007x over previous
#include <cuda_runtime.h>
#include <cstdint>

#define HID   2048
#define INTER 8192
#define RANK  16
#define SEQ   2048
#define NB    4
#define MTOT  8192          // NB*SEQ rows
#define KSEL  10

// ---------------- scratch (static device globals; no allocation) -------------
__device__ float g_x2[(size_t)MTOT * INTER];   // 256 MB relu(up) activations
__device__ float g_tup[MTOT * RANK];
__device__ float g_tdown[MTOT * RANK];
__device__ int   g_zero[NB * INTER];
__device__ int   g_topk[NB * KSEL];

// ---------------- helpers ----------------------------------------------------
__global__ void zinit_kernel() {
    int i = blockIdx.x * blockDim.x + threadIdx.x;
    if (i < NB * INTER) g_zero[i] = 0;
}

// T[M,16] = X[M,K] @ A[K,16]   (32 rows / block, 256 threads)
__global__ __launch_bounds__(256) void gemm_rank16(
    const float* __restrict__ X, const float* __restrict__ A,
    float* __restrict__ T, int K)
{
    __shared__ float xs[32][64];
    __shared__ float as[64][16];
    const int tid = threadIdx.x;
    const int bm  = blockIdx.x * 32;
    const int r0  = tid >> 4;        // 0..15
    const int r1  = r0 + 16;         // 16..31
    const int col = tid & 15;
    float acc0 = 0.f, acc1 = 0.f;

    for (int k0 = 0; k0 < K; k0 += 64) {
        __syncthreads();
#pragma unroll
        for (int r = 0; r < 2; r++) {
            int i4  = tid * 2 + r;               // 0..511 float4s of the 32x64 tile
            int row = i4 >> 4;
            int c   = (i4 & 15) * 4;
            *(float4*)&xs[row][c] =
                *(const float4*)(X + (size_t)(bm + row) * K + k0 + c);
        }
        {
            int row = tid >> 2;                  // 64x16 tile: 256 float4s
            int c   = (tid & 3) * 4;
            *(float4*)&as[row][c] =
                *(const float4*)(A + (size_t)(k0 + row) * RANK + c);
        }
        __syncthreads();
#pragma unroll 16
        for (int kk = 0; kk < 64; kk++) {
            float w = as[kk][col];
            acc0 = fmaf(xs[r0][kk], w, acc0);
            acc1 = fmaf(xs[r1][kk], w, acc1);
        }
    }
    T[(bm + r0) * RANK + col] = acc0;
    T[(bm + r1) * RANK + col] = acc1;
}

// C[M,N] = A[M,K] @ W[K,N] + loraT[M,16] @ loraB[16,N]
// RELU_COUNT: apply relu, accumulate per-(batch,channel) zero counts.
// Tiles: 128x128x16, 256 threads, 8x8 per thread.
template <bool RELU_COUNT>
__global__ __launch_bounds__(256) void gemm_lora(
    const float* __restrict__ A, const float* __restrict__ W,
    const float* __restrict__ loraT, const float* __restrict__ loraB,
    float* __restrict__ C, int N, int K)
{
    __shared__ float As[16][128];
    __shared__ float Ws[16][128];
    __shared__ float Ts[128][16];
    __shared__ float Bsh[16][128];
    __shared__ int   zc[128];

    const int tid = threadIdx.x;
    const int bm  = blockIdx.y * 128;
    const int bn  = blockIdx.x * 128;

    // preload LoRA tiles (each 2048 floats = 512 float4, 2 per thread)
#pragma unroll
    for (int r = 0; r < 2; r++) {
        int i4 = tid * 2 + r;
        int trow = i4 >> 2, tc = (i4 & 3) * 4;
        float4 v = *(const float4*)(loraT + (size_t)(bm + trow) * RANK + tc);
        Ts[trow][tc]   = v.x; Ts[trow][tc+1] = v.y;
        Ts[trow][tc+2] = v.z; Ts[trow][tc+3] = v.w;
        int br = i4 >> 5, bc = (i4 & 31) * 4;
        *(float4*)&Bsh[br][bc] = *(const float4*)(loraB + (size_t)br * N + bn + bc);
    }

    float acc[8][8];
#pragma unroll
    for (int i = 0; i < 8; i++)
#pragma unroll
        for (int j = 0; j < 8; j++) acc[i][j] = 0.f;

    const int rowb = (tid >> 4) * 8;
    const int colb = (tid & 15) * 8;

    for (int k0 = 0; k0 < K; k0 += 16) {
        __syncthreads();
#pragma unroll
        for (int r = 0; r < 2; r++) {
            int i4 = tid * 2 + r;
            int arow = i4 >> 2, ak = (i4 & 3) * 4;
            float4 v = *(const float4*)(A + (size_t)(bm + arow) * K + k0 + ak);
            As[ak][arow]   = v.x; As[ak+1][arow] = v.y;
            As[ak+2][arow] = v.z; As[ak+3][arow] = v.w;
            int wr = i4 >> 5, wc = (i4 & 31) * 4;
            *(float4*)&Ws[wr][wc] = *(const float4*)(W + (size_t)(k0 + wr) * N + bn + wc);
        }
        __syncthreads();
#pragma unroll
        for (int kk = 0; kk < 16; kk++) {
            float ra[8], rw[8];
#pragma unroll
            for (int i = 0; i < 8; i++) ra[i] = As[kk][rowb + i];
#pragma unroll
            for (int j = 0; j < 8; j++) rw[j] = Ws[kk][colb + j];
#pragma unroll
            for (int i = 0; i < 8; i++)
#pragma unroll
                for (int j = 0; j < 8; j++)
                    acc[i][j] = fmaf(ra[i], rw[j], acc[i][j]);
        }
    }

    // rank-16 LoRA epilogue
#pragma unroll
    for (int r = 0; r < RANK; r++) {
        float ta[8], bb[8];
#pragma unroll
        for (int i = 0; i < 8; i++) ta[i] = Ts[rowb + i][r];
#pragma unroll
        for (int j = 0; j < 8; j++) bb[j] = Bsh[r][colb + j];
#pragma unroll
        for (int i = 0; i < 8; i++)
#pragma unroll
            for (int j = 0; j < 8; j++)
                acc[i][j] = fmaf(ta[i], bb[j], acc[i][j]);
    }

    if (RELU_COUNT) {
        __syncthreads();
        if (tid < 128) zc[tid] = 0;
        __syncthreads();
        int cnt[8];
#pragma unroll
        for (int j = 0; j < 8; j++) cnt[j] = 0;
#pragma unroll
        for (int i = 0; i < 8; i++) {
#pragma unroll
            for (int j = 0; j < 8; j++) {
                float v = fmaxf(acc[i][j], 0.0f);
                acc[i][j] = v;
                cnt[j] += (v == 0.0f);
            }
            float* cp = C + (size_t)(bm + rowb + i) * N + bn + colb;
            *(float4*)cp       = make_float4(acc[i][0], acc[i][1], acc[i][2], acc[i][3]);
            *(float4*)(cp + 4) = make_float4(acc[i][4], acc[i][5], acc[i][6], acc[i][7]);
        }
#pragma unroll
        for (int j = 0; j < 8; j++) atomicAdd(&zc[colb + j], cnt[j]);
        __syncthreads();
        if (tid < 128) {
            int b = bm / SEQ;                       // 128-row tiles never straddle batches
            atomicAdd(&g_zero[b * INTER + bn + tid], zc[tid]);
        }
    } else {
#pragma unroll
        for (int i = 0; i < 8; i++) {
            float* cp = C + (size_t)(bm + rowb + i) * N + bn + colb;
            *(float4*)cp       = make_float4(acc[i][0], acc[i][1], acc[i][2], acc[i][3]);
            *(float4*)(cp + 4) = make_float4(acc[i][4], acc[i][5], acc[i][6], acc[i][7]);
        }
    }
}

// per-batch selection of KSEL channels with fewest zeros; jax.lax.top_k order:
// ascending zero-count, ties broken by lower channel index.
__global__ void topk_kernel() {
    const int b   = blockIdx.x;
    const int tid = threadIdx.x;
    __shared__ unsigned red[256];
    __shared__ int chosen[KSEL];

    for (int sel = 0; sel < KSEL; sel++) {
        unsigned best = 0xFFFFFFFFu;
        for (int j = tid; j < INTER; j += 256) {
            bool skip = false;
            for (int c = 0; c < sel; c++)
                if (chosen[c] == j) skip = true;
            if (!skip) {
                unsigned key = ((unsigned)g_zero[b * INTER + j] << 13) | (unsigned)j;
                best = min(best, key);
            }
        }
        red[tid] = best;
        __syncthreads();
        for (int s = 128; s > 0; s >>= 1) {
            if (tid < s) red[tid] = min(red[tid], red[tid + s]);
            __syncthreads();
        }
        if (tid == 0) {
            chosen[sel] = (int)(red[0] & 8191u);
            g_topk[b * KSEL + sel] = chosen[sel];
        }
        __syncthreads();
    }
}

__global__ void gather_kernel(float* __restrict__ out) {
    int idx = blockIdx.x * blockDim.x + threadIdx.x;   // [0, NB*SEQ*KSEL)
    if (idx >= NB * SEQ * KSEL) return;
    int i   = idx % KSEL;
    int row = idx / KSEL;                              // global token row
    int b   = row / SEQ;
    out[idx] = g_x2[(size_t)row * INTER + g_topk[b * KSEL + i]];
}

// ---------------- launch ------------------------------------------------------
extern "C" void kernel_launch(void* const* d_in, const int* in_sizes, int n_in,
                              void* d_out, int out_size)
{
    const float* x1        = (const float*)d_in[0];
    const float* w_up      = (const float*)d_in[1];
    const float* w_up_la   = (const float*)d_in[2];
    const float* w_up_lb   = (const float*)d_in[3];
    const float* w_down    = (const float*)d_in[4];
    const float* w_down_la = (const float*)d_in[5];
    const float* w_down_lb = (const float*)d_in[6];
    float* out = (float*)d_out;

    float *px2, *ptup, *ptdown;
    cudaGetSymbolAddress((void**)&px2,    g_x2);
    cudaGetSymbolAddress((void**)&ptup,   g_tup);
    cudaGetSymbolAddress((void**)&ptdown, g_tdown);

    zinit_kernel<<<(NB * INTER + 1023) / 1024, 1024>>>();

    // t_up = x1 @ w_up_lora_a
    gemm_rank16<<<MTOT / 32, 256>>>(x1, w_up_la, ptup, HID);

    // x2 = relu(x1 @ w_up + t_up @ w_up_lora_b), plus per-channel zero counts
    gemm_lora<true><<<dim3(INTER / 128, MTOT / 128), 256>>>(
        x1, w_up, ptup, w_up_lb, px2, INTER, HID);

    // t_down = x2 @ w_down_lora_a
    gemm_rank16<<<MTOT / 32, 256>>>(px2, w_down_la, ptdown, INTER);

    // y2 = x2 @ w_down + t_down @ w_down_lora_b  -> first output
    gemm_lora<false><<<dim3(HID / 128, MTOT / 128), 256>>>(
        px2, w_down, ptdown, w_down_lb, out, HID, INTER);

    // top-10 channels per batch, then gather -> second output
    topk_kernel<<<NB, 256>>>();
    gather_kernel<<<(NB * SEQ * KSEL + 255) / 256, 256>>>(out + (size_t)MTOT * HID);
}

// round 6
// speedup vs baseline: 2.1459x; 2.1445x over previous
#include <cuda_runtime.h>
#include <cuda_bf16.h>
#include <cstdint>

#define HID 2048
#define INTER 8192
#define RANK 16
#define SEQ 2048
#define NB 4
#define MTOT 8192
#define KSEL 10

#define BM 128
#define BN 128
#define BK 32
#define LDSM_STRIDE 40                  // bf16 elems per smem row (80 bytes)
#define TILE_B (128 * LDSM_STRIDE * 2)  // 10240 bytes per operand tile
#define STAGE_B (4 * TILE_B)            // Ah, Al, Bh, Bl
#define NSTAGE 3
#define DYN_SMEM (NSTAGE * STAGE_B)     // 122880

// ---------------- device scratch ----------------
__device__ float g_x2[(size_t)MTOT * INTER];
__device__ __nv_bfloat16 g_x2h[(size_t)MTOT * INTER];
__device__ __nv_bfloat16 g_x2l[(size_t)MTOT * INTER];
__device__ __nv_bfloat16 g_x1h[(size_t)MTOT * HID];
__device__ __nv_bfloat16 g_x1l[(size_t)MTOT * HID];
__device__ float g_tup[MTOT * RANK];
__device__ float g_tdown[MTOT * RANK];
__device__ __nv_bfloat16 g_tuph[MTOT * 32];
__device__ __nv_bfloat16 g_tupl[MTOT * 32];
__device__ __nv_bfloat16 g_tdnh[MTOT * 32];
__device__ __nv_bfloat16 g_tdnl[MTOT * 32];
__device__ __nv_bfloat16 g_wupT_h[(size_t)INTER * HID];
__device__ __nv_bfloat16 g_wupT_l[(size_t)INTER * HID];
__device__ __nv_bfloat16 g_wdnT_h[(size_t)HID * INTER];
__device__ __nv_bfloat16 g_wdnT_l[(size_t)HID * INTER];
__device__ __nv_bfloat16 g_lubh[INTER * 32];
__device__ __nv_bfloat16 g_lubl[INTER * 32];
__device__ __nv_bfloat16 g_ldbh[HID * 32];
__device__ __nv_bfloat16 g_ldbl[HID * 32];
__device__ int g_zero[NB * INTER];
__device__ int g_topk[NB * KSEL];

// ---------------- helpers ----------------
__device__ __forceinline__ uint32_t smem_u32(const void* p) {
    uint32_t a;
    asm("{ .reg .u64 t; cvta.to.shared.u64 t, %1; cvt.u32.u64 %0, t; }" : "=r"(a) : "l"(p));
    return a;
}
__device__ __forceinline__ void split1(float x, __nv_bfloat16& h, __nv_bfloat16& l) {
    h = __float2bfloat16(x);
    l = __float2bfloat16(x - __bfloat162float(h));
}
__device__ __forceinline__ uint32_t packbf(__nv_bfloat16 a, __nv_bfloat16 b) {
    __nv_bfloat162 t = __halves2bfloat162(a, b);
    return *reinterpret_cast<uint32_t*>(&t);
}
__device__ __forceinline__ void cpasync16(uint32_t dst, const void* src) {
    asm volatile("cp.async.cg.shared.global [%0], [%1], 16;" :: "r"(dst), "l"(src));
}
__device__ __forceinline__ void ldsm4(uint32_t (&r)[4], uint32_t addr) {
    asm volatile("ldmatrix.sync.aligned.m8n8.x4.shared.b16 {%0,%1,%2,%3}, [%4];"
                 : "=r"(r[0]), "=r"(r[1]), "=r"(r[2]), "=r"(r[3]) : "r"(addr));
}
__device__ __forceinline__ void mma16816(float (&d)[4], const uint32_t (&a)[4],
                                         const uint32_t* b) {
    asm volatile(
        "mma.sync.aligned.m16n8k16.row.col.f32.bf16.bf16.f32 "
        "{%0,%1,%2,%3},{%4,%5,%6,%7},{%8,%9},{%0,%1,%2,%3};"
        : "+f"(d[0]), "+f"(d[1]), "+f"(d[2]), "+f"(d[3])
        : "r"(a[0]), "r"(a[1]), "r"(a[2]), "r"(a[3]), "r"(b[0]), "r"(b[1]));
}

// ---------------- preprocessing kernels ----------------
__global__ __launch_bounds__(256) void transpose_split(
    const float* __restrict__ W, __nv_bfloat16* __restrict__ hiT,
    __nv_bfloat16* __restrict__ loT, int R, int C)
{
    __shared__ float t[32][33];
    const int tx = threadIdx.x & 31, ty = threadIdx.x >> 5;
    const int r0 = blockIdx.y * 32, c0 = blockIdx.x * 32;
#pragma unroll
    for (int i = 0; i < 4; i++) {
        int r = ty + i * 8;
        t[r][tx] = W[(size_t)(r0 + r) * C + c0 + tx];
    }
    __syncthreads();
#pragma unroll
    for (int i = 0; i < 4; i++) {
        int c = ty + i * 8;
        __nv_bfloat16 h, l;
        split1(t[tx][c], h, l);
        hiT[(size_t)(c0 + c) * R + r0 + tx] = h;
        loT[(size_t)(c0 + c) * R + r0 + tx] = l;
    }
}

__global__ void split_mat(const float* __restrict__ X, __nv_bfloat16* __restrict__ h,
                          __nv_bfloat16* __restrict__ l, size_t n4)
{
    size_t i = (size_t)blockIdx.x * blockDim.x + threadIdx.x;
    if (i >= n4) return;
    float4 v = *(const float4*)(X + i * 4);
    __nv_bfloat16 h0, h1, h2, h3, l0, l1, l2, l3;
    split1(v.x, h0, l0); split1(v.y, h1, l1);
    split1(v.z, h2, l2); split1(v.w, h3, l3);
    ((uint2*)h)[i] = make_uint2(packbf(h0, h1), packbf(h2, h3));
    ((uint2*)l)[i] = make_uint2(packbf(l0, l1), packbf(l2, l3));
}

// T[M][16] -> padded [M][32] bf16 h/l (cols 16..31 = 0)
__global__ void split_lora_t(const float* __restrict__ T, __nv_bfloat16* __restrict__ h,
                             __nv_bfloat16* __restrict__ l, int M)
{
    int i = blockIdx.x * blockDim.x + threadIdx.x;
    if (i >= M * 32) return;
    int j = i & 31;
    float v = (j < 16) ? T[(i >> 5) * 16 + j] : 0.0f;
    __nv_bfloat16 hh, ll;
    split1(v, hh, ll);
    h[i] = hh; l[i] = ll;
}

// W[16][N] -> padded transposed [N][32] bf16 h/l
__global__ void split_lora_b(const float* __restrict__ W, __nv_bfloat16* __restrict__ h,
                             __nv_bfloat16* __restrict__ l, int N)
{
    int i = blockIdx.x * blockDim.x + threadIdx.x;
    if (i >= N * 32) return;
    int n = i >> 5, j = i & 31;
    float v = (j < 16) ? W[(size_t)j * N + n] : 0.0f;
    __nv_bfloat16 hh, ll;
    split1(v, hh, ll);
    h[i] = hh; l[i] = ll;
}

__global__ void zinit_kernel() {
    int i = blockIdx.x * blockDim.x + threadIdx.x;
    if (i < NB * INTER) g_zero[i] = 0;
}

// ---------------- rank-16 GEMM (fp32, bandwidth-style) ----------------
__global__ __launch_bounds__(256) void rank16_v3(
    const float* __restrict__ X, const float* __restrict__ A16,
    float* __restrict__ T, int K)
{
    const int wid = threadIdx.x >> 5, lane = threadIdx.x & 31;
    const int row0 = (blockIdx.x * 8 + wid) * 4;
    float acc[4][16];
#pragma unroll
    for (int r = 0; r < 4; r++)
#pragma unroll
        for (int j = 0; j < 16; j++) acc[r][j] = 0.0f;
    for (int k0 = lane * 4; k0 < K; k0 += 128) {
        float4 xv[4];
#pragma unroll
        for (int r = 0; r < 4; r++) xv[r] = *(const float4*)(X + (size_t)(row0 + r) * K + k0);
#pragma unroll
        for (int e = 0; e < 4; e++) {
            const float* Ar = A16 + (size_t)(k0 + e) * 16;
            float av[16];
#pragma unroll
            for (int j = 0; j < 16; j += 4) {
                float4 a = *(const float4*)(Ar + j);
                av[j] = a.x; av[j + 1] = a.y; av[j + 2] = a.z; av[j + 3] = a.w;
            }
#pragma unroll
            for (int r = 0; r < 4; r++) {
                float xs = (e == 0) ? xv[r].x : (e == 1) ? xv[r].y : (e == 2) ? xv[r].z : xv[r].w;
#pragma unroll
                for (int j = 0; j < 16; j++) acc[r][j] = fmaf(xs, av[j], acc[r][j]);
            }
        }
    }
#pragma unroll
    for (int r = 0; r < 4; r++)
#pragma unroll
        for (int j = 0; j < 16; j++)
#pragma unroll
            for (int o = 16; o > 0; o >>= 1)
                acc[r][j] += __shfl_xor_sync(0xffffffffu, acc[r][j], o);
    if (lane == 0)
#pragma unroll
        for (int r = 0; r < 4; r++)
#pragma unroll
            for (int j = 0; j < 16; j++) T[(size_t)(row0 + r) * 16 + j] = acc[r][j];
}

// ---------------- main mma.sync GEMM ----------------
// C[M,N] = A @ BT^T + loraT @ lbT^T, bf16 2-term split (AhBh + AlBh + AhBl)
template <bool RC>
__global__ __launch_bounds__(256) void mma_gemm(
    const __nv_bfloat16* __restrict__ Ah, const __nv_bfloat16* __restrict__ Al,
    const __nv_bfloat16* __restrict__ Bh, const __nv_bfloat16* __restrict__ Bl,
    const __nv_bfloat16* __restrict__ lth, const __nv_bfloat16* __restrict__ ltl,
    const __nv_bfloat16* __restrict__ lbh, const __nv_bfloat16* __restrict__ lbl,
    float* __restrict__ C, uint32_t* __restrict__ x2h, uint32_t* __restrict__ x2l,
    int N, int K)
{
    extern __shared__ char smem[];
    const uint32_t sbase = smem_u32(smem);
    const int tid = threadIdx.x, lane = tid & 31, wid = tid >> 5;
    const int wm = wid >> 2, wn = wid & 3;
    const int bm = blockIdx.y * BM, bn = blockIdx.x * BN;
    const int nmain = K / BK, ntot = nmain + 1;

    // ---- producer: one chunk -> one stage ----
    auto issue = [&](int c) {
        const __nv_bfloat16 *pa0, *pa1, *pb0, *pb1;
        int sa, sb;
        if (c < nmain) {
            size_t ao = (size_t)bm * K + c * BK, bo = (size_t)bn * K + c * BK;
            pa0 = Ah + ao; pa1 = Al + ao; sa = K;
            pb0 = Bh + bo; pb1 = Bl + bo; sb = K;
        } else {
            pa0 = lth + (size_t)bm * 32; pa1 = ltl + (size_t)bm * 32; sa = 32;
            pb0 = lbh + (size_t)bn * 32; pb1 = lbl + (size_t)bn * 32; sb = 32;
        }
        uint32_t stage = sbase + (c % NSTAGE) * STAGE_B;
#pragma unroll
        for (int q = 0; q < 8; q++) {
            int qi = tid + q * 256;
            int arr = qi >> 9;          // 0:Ah 1:Al 2:Bh 3:Bl
            int idx = qi & 511;
            int r = idx >> 2, cc = idx & 3;
            const __nv_bfloat16* src;
            if (arr == 0)      src = pa0 + (size_t)r * sa + cc * 8;
            else if (arr == 1) src = pa1 + (size_t)r * sa + cc * 8;
            else if (arr == 2) src = pb0 + (size_t)r * sb + cc * 8;
            else               src = pb1 + (size_t)r * sb + cc * 8;
            cpasync16(stage + arr * TILE_B + r * (LDSM_STRIDE * 2) + cc * 16, src);
        }
        asm volatile("cp.async.commit_group;");
    };

    issue(0);
    issue(1);

    float acc[4][4][4];
#pragma unroll
    for (int mf = 0; mf < 4; mf++)
#pragma unroll
        for (int nf = 0; nf < 4; nf++)
#pragma unroll
            for (int q = 0; q < 4; q++) acc[mf][nf][q] = 0.0f;

    for (int c = 0; c < ntot; c++) {
        asm volatile("cp.async.wait_group 1;" ::: "memory");
        __syncthreads();
        if (c + 2 < ntot) issue(c + 2);
        const uint32_t stage = sbase + (c % NSTAGE) * STAGE_B;
#pragma unroll
        for (int s = 0; s < 2; s++) {
            uint32_t ah[4][4], al[4][4], bh[4][2], bl[4][2];
#pragma unroll
            for (int mf = 0; mf < 4; mf++) {
                uint32_t ra = stage +
                    ((wm * 64 + mf * 16 + (lane & 15)) * LDSM_STRIDE +
                     s * 16 + (lane >> 4) * 8) * 2;
                ldsm4(ah[mf], ra);
                ldsm4(al[mf], ra + TILE_B);
            }
#pragma unroll
            for (int nf16 = 0; nf16 < 2; nf16++) {
                uint32_t rb = stage + 2 * TILE_B +
                    ((wn * 32 + nf16 * 16 + (lane & 7) + (((lane >> 4) & 1) << 3)) * LDSM_STRIDE +
                     s * 16 + ((lane >> 3) & 1) * 8) * 2;
                uint32_t t[4];
                ldsm4(t, rb);
                bh[nf16 * 2][0] = t[0]; bh[nf16 * 2][1] = t[1];
                bh[nf16 * 2 + 1][0] = t[2]; bh[nf16 * 2 + 1][1] = t[3];
                ldsm4(t, rb + TILE_B);
                bl[nf16 * 2][0] = t[0]; bl[nf16 * 2][1] = t[1];
                bl[nf16 * 2 + 1][0] = t[2]; bl[nf16 * 2 + 1][1] = t[3];
            }
#pragma unroll
            for (int mf = 0; mf < 4; mf++)
#pragma unroll
                for (int nf = 0; nf < 4; nf++) {
                    mma16816(acc[mf][nf], ah[mf], bh[nf]);
                    mma16816(acc[mf][nf], al[mf], bh[nf]);
                    mma16816(acc[mf][nf], ah[mf], bl[nf]);
                }
        }
    }

    // ---- epilogue ----
    const int r0 = lane >> 2, c0 = (lane & 3) * 2;
    if (RC) {
        __shared__ int zc[BN];
        __syncthreads();
        if (tid < BN) zc[tid] = 0;
        __syncthreads();
        int cnt0[4] = {0, 0, 0, 0}, cnt1[4] = {0, 0, 0, 0};
#pragma unroll
        for (int mf = 0; mf < 4; mf++)
#pragma unroll
            for (int nf = 0; nf < 4; nf++) {
                float v0 = fmaxf(acc[mf][nf][0], 0.0f);
                float v1 = fmaxf(acc[mf][nf][1], 0.0f);
                float v2 = fmaxf(acc[mf][nf][2], 0.0f);
                float v3 = fmaxf(acc[mf][nf][3], 0.0f);
                cnt0[nf] += (v0 == 0.0f) + (v2 == 0.0f);
                cnt1[nf] += (v1 == 0.0f) + (v3 == 0.0f);
                int ra = bm + wm * 64 + mf * 16 + r0;
                int col = bn + wn * 32 + nf * 8 + c0;
                *(float2*)&C[(size_t)ra * N + col] = make_float2(v0, v1);
                *(float2*)&C[(size_t)(ra + 8) * N + col] = make_float2(v2, v3);
                __nv_bfloat16 h0, h1, h2, h3, l0, l1, l2, l3;
                split1(v0, h0, l0); split1(v1, h1, l1);
                split1(v2, h2, l2); split1(v3, h3, l3);
                size_t pa = (size_t)ra * (N / 2) + (col >> 1);
                size_t pb = (size_t)(ra + 8) * (N / 2) + (col >> 1);
                x2h[pa] = packbf(h0, h1); x2l[pa] = packbf(l0, l1);
                x2h[pb] = packbf(h2, h3); x2l[pb] = packbf(l2, l3);
            }
#pragma unroll
        for (int nf = 0; nf < 4; nf++) {
            atomicAdd(&zc[wn * 32 + nf * 8 + c0], cnt0[nf]);
            atomicAdd(&zc[wn * 32 + nf * 8 + c0 + 1], cnt1[nf]);
        }
        __syncthreads();
        if (tid < BN) {
            int b = bm / SEQ;
            atomicAdd(&g_zero[b * INTER + bn + tid], zc[tid]);
        }
    } else {
#pragma unroll
        for (int mf = 0; mf < 4; mf++)
#pragma unroll
            for (int nf = 0; nf < 4; nf++) {
                int ra = bm + wm * 64 + mf * 16 + r0;
                int col = bn + wn * 32 + nf * 8 + c0;
                *(float2*)&C[(size_t)ra * N + col] = make_float2(acc[mf][nf][0], acc[mf][nf][1]);
                *(float2*)&C[(size_t)(ra + 8) * N + col] = make_float2(acc[mf][nf][2], acc[mf][nf][3]);
            }
    }
}

// ---------------- topk + gather ----------------
__global__ void topk_kernel() {
    const int b = blockIdx.x, tid = threadIdx.x;
    __shared__ unsigned red[256];
    __shared__ int chosen[KSEL];
    for (int sel = 0; sel < KSEL; sel++) {
        unsigned best = 0xFFFFFFFFu;
        for (int j = tid; j < INTER; j += 256) {
            bool skip = false;
            for (int c = 0; c < sel; c++) if (chosen[c] == j) skip = true;
            if (!skip) best = min(best, ((unsigned)g_zero[b * INTER + j] << 13) | (unsigned)j);
        }
        red[tid] = best;
        __syncthreads();
        for (int s = 128; s > 0; s >>= 1) {
            if (tid < s) red[tid] = min(red[tid], red[tid + s]);
            __syncthreads();
        }
        if (tid == 0) { chosen[sel] = (int)(red[0] & 8191u); g_topk[b * KSEL + sel] = chosen[sel]; }
        __syncthreads();
    }
}

__global__ void gather_kernel(float* __restrict__ out) {
    int idx = blockIdx.x * blockDim.x + threadIdx.x;
    if (idx >= NB * SEQ * KSEL) return;
    int i = idx % KSEL, row = idx / KSEL, b = row / SEQ;
    out[idx] = g_x2[(size_t)row * INTER + g_topk[b * KSEL + i]];
}

// ---------------- launch ----------------
extern "C" void kernel_launch(void* const* d_in, const int* in_sizes, int n_in,
                              void* d_out, int out_size)
{
    const float* x1 = (const float*)d_in[0];
    const float* w_up = (const float*)d_in[1];
    const float* w_up_la = (const float*)d_in[2];
    const float* w_up_lb = (const float*)d_in[3];
    const float* w_down = (const float*)d_in[4];
    const float* w_down_la = (const float*)d_in[5];
    const float* w_down_lb = (const float*)d_in[6];
    float* out = (float*)d_out;

    float *px2, *ptup, *ptdown;
    __nv_bfloat16 *x1h, *x1l, *x2h, *x2l, *uh, *ul, *dh, *dl;
    __nv_bfloat16 *tuph, *tupl, *tdnh, *tdnl, *ubh, *ubl, *dbh, *dbl;
    cudaGetSymbolAddress((void**)&px2, g_x2);
    cudaGetSymbolAddress((void**)&ptup, g_tup);
    cudaGetSymbolAddress((void**)&ptdown, g_tdown);
    cudaGetSymbolAddress((void**)&x1h, g_x1h);
    cudaGetSymbolAddress((void**)&x1l, g_x1l);
    cudaGetSymbolAddress((void**)&x2h, g_x2h);
    cudaGetSymbolAddress((void**)&x2l, g_x2l);
    cudaGetSymbolAddress((void**)&uh, g_wupT_h);
    cudaGetSymbolAddress((void**)&ul, g_wupT_l);
    cudaGetSymbolAddress((void**)&dh, g_wdnT_h);
    cudaGetSymbolAddress((void**)&dl, g_wdnT_l);
    cudaGetSymbolAddress((void**)&tuph, g_tuph);
    cudaGetSymbolAddress((void**)&tupl, g_tupl);
    cudaGetSymbolAddress((void**)&tdnh, g_tdnh);
    cudaGetSymbolAddress((void**)&tdnl, g_tdnl);
    cudaGetSymbolAddress((void**)&ubh, g_lubh);
    cudaGetSymbolAddress((void**)&ubl, g_lubl);
    cudaGetSymbolAddress((void**)&dbh, g_ldbh);
    cudaGetSymbolAddress((void**)&dbl, g_ldbl);

    cudaFuncSetAttribute(mma_gemm<true>, cudaFuncAttributeMaxDynamicSharedMemorySize, DYN_SMEM);
    cudaFuncSetAttribute(mma_gemm<false>, cudaFuncAttributeMaxDynamicSharedMemorySize, DYN_SMEM);

    // preprocessing
    transpose_split<<<dim3(INTER / 32, HID / 32), 256>>>(w_up, uh, ul, HID, INTER);
    transpose_split<<<dim3(HID / 32, INTER / 32), 256>>>(w_down, dh, dl, INTER, HID);
    split_lora_b<<<(INTER * 32 + 255) / 256, 256>>>(w_up_lb, ubh, ubl, INTER);
    split_lora_b<<<(HID * 32 + 255) / 256, 256>>>(w_down_lb, dbh, dbl, HID);
    split_mat<<<(int)(((size_t)MTOT * HID / 4 + 255) / 256), 256>>>(
        x1, x1h, x1l, (size_t)MTOT * HID / 4);
    zinit_kernel<<<(NB * INTER + 1023) / 1024, 1024>>>();

    // up path
    rank16_v3<<<MTOT / 32, 256>>>(x1, w_up_la, ptup, HID);
    split_lora_t<<<(MTOT * 32 + 255) / 256, 256>>>(ptup, tuph, tupl, MTOT);
    mma_gemm<true><<<dim3(INTER / BN, MTOT / BM), 256, DYN_SMEM>>>(
        x1h, x1l, uh, ul, tuph, tupl, ubh, ubl,
        px2, (uint32_t*)x2h, (uint32_t*)x2l, INTER, HID);

    // down path
    rank16_v3<<<MTOT / 32, 256>>>(px2, w_down_la, ptdown, INTER);
    split_lora_t<<<(MTOT * 32 + 255) / 256, 256>>>(ptdown, tdnh, tdnl, MTOT);
    mma_gemm<false><<<dim3(HID / BN, MTOT / BM), 256, DYN_SMEM>>>(
        x2h, x2l, dh, dl, tdnh, tdnl, dbh, dbl,
        out, nullptr, nullptr, HID, INTER);

    // outputs 2: top-k gather
    topk_kernel<<<NB, 256>>>();
    gather_kernel<<<(NB * SEQ * KSEL + 255) / 256, 256>>>(out + (size_t)MTOT * HID);
}

// round 7
// speedup vs baseline: 2.3207x; 1.0814x over previous
#include <cuda_runtime.h>
#include <cuda_bf16.h>
#include <cuda_fp16.h>
#include <cstdint>

#define HID 2048
#define INTER 8192
#define RANK 16
#define SEQ 2048
#define NB 4
#define MTOT 8192
#define KSEL 10

#define BM 128
#define BN 128
#define BK 32
#define LDSM_STRIDE 40
#define TILE_B (128 * LDSM_STRIDE * 2)
#define STAGE_B (4 * TILE_B)
#define NSTAGE 3
#define DYN_SMEM (NSTAGE * STAGE_B)

// ---------------- device scratch ----------------
__device__ float g_x2[(size_t)MTOT * INTER];
__device__ __half g_x2f[(size_t)MTOT * INTER];
__device__ __half g_x2fs[(size_t)MTOT * INTER];
__device__ __nv_bfloat16 g_x1h[(size_t)MTOT * HID];
__device__ __nv_bfloat16 g_x1l[(size_t)MTOT * HID];
__device__ __nv_bfloat16 g_wupT_h[(size_t)INTER * HID];
__device__ __nv_bfloat16 g_wupT_l[(size_t)INTER * HID];
__device__ __half g_wdnT_f[(size_t)HID * INTER];
__device__ __half g_wdnT_ls[(size_t)HID * INTER];
__device__ __nv_bfloat16 g_lth[MTOT * 32];
__device__ __nv_bfloat16 g_ltl[MTOT * 32];
__device__ __half g_ltf[MTOT * 32];
__device__ __half g_ltfs[MTOT * 32];
__device__ __nv_bfloat16 g_lubh[INTER * 32];
__device__ __nv_bfloat16 g_lubl[INTER * 32];
__device__ __half g_ldbf[HID * 32];
__device__ __half g_ldbls[HID * 32];
__device__ int g_zero[NB * INTER];
__device__ int g_topk[NB * KSEL];

// ---------------- helpers ----------------
__device__ __forceinline__ uint32_t smem_u32(const void* p) {
    uint32_t a;
    asm("{ .reg .u64 t; cvta.to.shared.u64 t, %1; cvt.u32.u64 %0, t; }" : "=r"(a) : "l"(p));
    return a;
}
__device__ __forceinline__ void split1(float x, __nv_bfloat16& h, __nv_bfloat16& l) {
    h = __float2bfloat16(x);
    l = __float2bfloat16(x - __bfloat162float(h));
}
__device__ __forceinline__ void split1f(float x, __half& h, __half& ls) {
    h = __float2half(x);
    ls = __float2half((x - __half2float(h)) * 1024.0f);
}
__device__ __forceinline__ uint32_t packbf(__nv_bfloat16 a, __nv_bfloat16 b) {
    __nv_bfloat162 t = __halves2bfloat162(a, b);
    return *reinterpret_cast<uint32_t*>(&t);
}
__device__ __forceinline__ uint32_t packh(__half a, __half b) {
    __half2 t = __halves2half2(a, b);
    return *reinterpret_cast<uint32_t*>(&t);
}
__device__ __forceinline__ void cpasync16(uint32_t dst, const void* src) {
    asm volatile("cp.async.cg.shared.global [%0], [%1], 16;" :: "r"(dst), "l"(src));
}
__device__ __forceinline__ void ldsm4(uint32_t (&r)[4], uint32_t addr) {
    asm volatile("ldmatrix.sync.aligned.m8n8.x4.shared.b16 {%0,%1,%2,%3}, [%4];"
                 : "=r"(r[0]), "=r"(r[1]), "=r"(r[2]), "=r"(r[3]) : "r"(addr));
}
__device__ __forceinline__ void mma_bf(float (&d)[4], const uint32_t (&a)[4], const uint32_t* b) {
    asm volatile("mma.sync.aligned.m16n8k16.row.col.f32.bf16.bf16.f32 "
                 "{%0,%1,%2,%3},{%4,%5,%6,%7},{%8,%9},{%0,%1,%2,%3};"
                 : "+f"(d[0]), "+f"(d[1]), "+f"(d[2]), "+f"(d[3])
                 : "r"(a[0]), "r"(a[1]), "r"(a[2]), "r"(a[3]), "r"(b[0]), "r"(b[1]));
}
__device__ __forceinline__ void mma_fp(float (&d)[4], const uint32_t (&a)[4], const uint32_t* b) {
    asm volatile("mma.sync.aligned.m16n8k16.row.col.f32.f16.f16.f32 "
                 "{%0,%1,%2,%3},{%4,%5,%6,%7},{%8,%9},{%0,%1,%2,%3};"
                 : "+f"(d[0]), "+f"(d[1]), "+f"(d[2]), "+f"(d[3])
                 : "r"(a[0]), "r"(a[1]), "r"(a[2]), "r"(a[3]), "r"(b[0]), "r"(b[1]));
}

// ---------------- launch 1: w_up transpose + bf16 split ----------------
__global__ __launch_bounds__(256) void transpose_split_bf(
    const float* __restrict__ W, __nv_bfloat16* __restrict__ hiT,
    __nv_bfloat16* __restrict__ loT, int R, int C)
{
    __shared__ float t[32][33];
    const int tx = threadIdx.x & 31, ty = threadIdx.x >> 5;
    const int r0 = blockIdx.y * 32, c0 = blockIdx.x * 32;
#pragma unroll
    for (int i = 0; i < 4; i++) {
        int r = ty + i * 8;
        t[r][tx] = W[(size_t)(r0 + r) * C + c0 + tx];
    }
    __syncthreads();
#pragma unroll
    for (int i = 0; i < 4; i++) {
        int c = ty + i * 8;
        __nv_bfloat16 h, l;
        split1(t[tx][c], h, l);
        hiT[(size_t)(c0 + c) * R + r0 + tx] = h;
        loT[(size_t)(c0 + c) * R + r0 + tx] = l;
    }
}

// ---------------- launch 2: fused elementwise prep ----------------
// blocks: [0,16384) split x1 -> bf16 pair; [16384,17408) lora_b up;
// [17408,17536) zero-init counts; [17536,33920) transpose+f16-split w_down;
// [33920,34176) lora_b down (f16 scaled pair)
#define PREP_T0 16384
#define PREP_T1 (PREP_T0 + 1024)
#define PREP_T2 (PREP_T1 + 128)
#define PREP_T3 (PREP_T2 + 16384)
#define PREP_GRID (PREP_T3 + 256)
__global__ __launch_bounds__(256) void prep_fused(
    const float* __restrict__ x1, const float* __restrict__ w_up_lb,
    const float* __restrict__ w_down, const float* __restrict__ w_down_lb)
{
    __shared__ float t[32][33];
    const int bid = blockIdx.x, tid = threadIdx.x;
    if (bid < PREP_T0) {
        size_t i = (size_t)bid * 256 + tid;       // float4 index
        float4 v = *(const float4*)(x1 + i * 4);
        __nv_bfloat16 h0, h1, h2, h3, l0, l1, l2, l3;
        split1(v.x, h0, l0); split1(v.y, h1, l1);
        split1(v.z, h2, l2); split1(v.w, h3, l3);
        ((uint2*)g_x1h)[i] = make_uint2(packbf(h0, h1), packbf(h2, h3));
        ((uint2*)g_x1l)[i] = make_uint2(packbf(l0, l1), packbf(l2, l3));
    } else if (bid < PREP_T1) {
        int i = (bid - PREP_T0) * 256 + tid;       // INTER*32
        int n = i >> 5, j = i & 31;
        float v = (j < 16) ? w_up_lb[(size_t)j * INTER + n] : 0.0f;
        __nv_bfloat16 h, l;
        split1(v, h, l);
        g_lubh[i] = h; g_lubl[i] = l;
    } else if (bid < PREP_T2) {
        int i = (bid - PREP_T1) * 256 + tid;
        if (i < NB * INTER) g_zero[i] = 0;
    } else if (bid < PREP_T3) {
        int tb = bid - PREP_T2;
        int bx = tb & 63, by = tb >> 6;            // (HID/32, INTER/32)
        const int tx = tid & 31, ty = tid >> 5;
        const int r0 = by * 32, c0 = bx * 32;
#pragma unroll
        for (int i = 0; i < 4; i++) {
            int r = ty + i * 8;
            t[r][tx] = w_down[(size_t)(r0 + r) * HID + c0 + tx];
        }
        __syncthreads();
#pragma unroll
        for (int i = 0; i < 4; i++) {
            int c = ty + i * 8;
            __half h, ls;
            split1f(t[tx][c], h, ls);
            g_wdnT_f[(size_t)(c0 + c) * INTER + r0 + tx] = h;
            g_wdnT_ls[(size_t)(c0 + c) * INTER + r0 + tx] = ls;
        }
    } else {
        int i = (bid - PREP_T3) * 256 + tid;       // HID*32
        int n = i >> 5, j = i & 31;
        float v = (j < 16) ? w_down_lb[(size_t)j * HID + n] : 0.0f;
        __half h, ls;
        split1f(v, h, ls);
        g_ldbf[i] = h; g_ldbls[i] = ls;
    }
}

// ---------------- rank-16 GEMM, writes padded split LoRA-T directly ----------
template <bool F16OUT>
__global__ __launch_bounds__(256) void rank16_direct(
    const float* __restrict__ X, const float* __restrict__ A16, int K)
{
    const int wid = threadIdx.x >> 5, lane = threadIdx.x & 31;
    const int row0 = (blockIdx.x * 8 + wid) * 4;
    float acc[4][16];
#pragma unroll
    for (int r = 0; r < 4; r++)
#pragma unroll
        for (int j = 0; j < 16; j++) acc[r][j] = 0.0f;
    for (int k0 = lane * 4; k0 < K; k0 += 128) {
        float4 xv[4];
#pragma unroll
        for (int r = 0; r < 4; r++) xv[r] = *(const float4*)(X + (size_t)(row0 + r) * K + k0);
#pragma unroll
        for (int e = 0; e < 4; e++) {
            const float* Ar = A16 + (size_t)(k0 + e) * 16;
            float av[16];
#pragma unroll
            for (int j = 0; j < 16; j += 4) {
                float4 a = *(const float4*)(Ar + j);
                av[j] = a.x; av[j + 1] = a.y; av[j + 2] = a.z; av[j + 3] = a.w;
            }
#pragma unroll
            for (int r = 0; r < 4; r++) {
                float xs = (e == 0) ? xv[r].x : (e == 1) ? xv[r].y : (e == 2) ? xv[r].z : xv[r].w;
#pragma unroll
                for (int j = 0; j < 16; j++) acc[r][j] = fmaf(xs, av[j], acc[r][j]);
            }
        }
    }
#pragma unroll
    for (int r = 0; r < 4; r++)
#pragma unroll
        for (int j = 0; j < 16; j++)
#pragma unroll
            for (int o = 16; o > 0; o >>= 1)
                acc[r][j] += __shfl_xor_sync(0xffffffffu, acc[r][j], o);
    if (lane < 4) {
        int r = lane;
        size_t base = (size_t)(row0 + r) * 32;
#pragma unroll
        for (int j = 0; j < 16; j++) {
            float v = acc[r][j];
            if (F16OUT) {
                __half h = __float2half(v);
                g_ltf[base + j] = h;
                g_ltfs[base + j] = __float2half(v * 0.0009765625f);
                g_ltf[base + 16 + j] = __float2half(0.0f);
                g_ltfs[base + 16 + j] = __float2half(0.0f);
            } else {
                __nv_bfloat16 h, l;
                split1(v, h, l);
                g_lth[base + j] = h; g_ltl[base + j] = l;
                g_lth[base + 16 + j] = __float2bfloat16(0.0f);
                g_ltl[base + 16 + j] = __float2bfloat16(0.0f);
            }
        }
    }
}

// ---------------- main mma.sync GEMM ----------------
// F16=false (up):  bf16 3-term  A0*B0 + A1*B0 + A0*B1
// F16=true  (down): fp16 2-term A0*B0 + A1*B1  (A1=A*2^-10, B1=(B-Bh)*2^10)
template <bool RC, bool F16>
__global__ __launch_bounds__(256) void mma_gemm(
    const __nv_bfloat16* __restrict__ A0, const __nv_bfloat16* __restrict__ A1,
    const __nv_bfloat16* __restrict__ B0, const __nv_bfloat16* __restrict__ B1,
    const __nv_bfloat16* __restrict__ lt0, const __nv_bfloat16* __restrict__ lt1,
    const __nv_bfloat16* __restrict__ lb0, const __nv_bfloat16* __restrict__ lb1,
    float* __restrict__ C, int N, int K)
{
    extern __shared__ char smem[];
    const uint32_t sbase = smem_u32(smem);
    const int tid = threadIdx.x, lane = tid & 31, wid = tid >> 5;
    const int wm = wid >> 2, wn = wid & 3;
    const int bm = blockIdx.y * BM, bn = blockIdx.x * BN;
    const int nmain = K / BK, ntot = nmain + 1;

    auto issue = [&](int c) {
        const __nv_bfloat16 *pa0, *pa1, *pb0, *pb1;
        int sa, sb;
        if (c < nmain) {
            size_t ao = (size_t)bm * K + c * BK, bo = (size_t)bn * K + c * BK;
            pa0 = A0 + ao; pa1 = A1 + ao; sa = K;
            pb0 = B0 + bo; pb1 = B1 + bo; sb = K;
        } else {
            pa0 = lt0 + (size_t)bm * 32; pa1 = lt1 + (size_t)bm * 32; sa = 32;
            pb0 = lb0 + (size_t)bn * 32; pb1 = lb1 + (size_t)bn * 32; sb = 32;
        }
        uint32_t stage = sbase + (c % NSTAGE) * STAGE_B;
#pragma unroll
        for (int q = 0; q < 8; q++) {
            int qi = tid + q * 256;
            int arr = qi >> 9, idx = qi & 511;
            int r = idx >> 2, cc = idx & 3;
            const __nv_bfloat16* src;
            if (arr == 0)      src = pa0 + (size_t)r * sa + cc * 8;
            else if (arr == 1) src = pa1 + (size_t)r * sa + cc * 8;
            else if (arr == 2) src = pb0 + (size_t)r * sb + cc * 8;
            else               src = pb1 + (size_t)r * sb + cc * 8;
            cpasync16(stage + arr * TILE_B + r * (LDSM_STRIDE * 2) + cc * 16, src);
        }
        asm volatile("cp.async.commit_group;");
    };

    issue(0);
    issue(1);

    float acc[4][4][4];
#pragma unroll
    for (int mf = 0; mf < 4; mf++)
#pragma unroll
        for (int nf = 0; nf < 4; nf++)
#pragma unroll
            for (int q = 0; q < 4; q++) acc[mf][nf][q] = 0.0f;

    for (int c = 0; c < ntot; c++) {
        asm volatile("cp.async.wait_group 1;" ::: "memory");
        __syncthreads();
        if (c + 2 < ntot) issue(c + 2);
        const uint32_t stage = sbase + (c % NSTAGE) * STAGE_B;
#pragma unroll
        for (int s = 0; s < 2; s++) {
            uint32_t ah[4][4], al[4][4], bh[4][2], bl[4][2];
#pragma unroll
            for (int mf = 0; mf < 4; mf++) {
                uint32_t ra = stage +
                    ((wm * 64 + mf * 16 + (lane & 15)) * LDSM_STRIDE +
                     s * 16 + (lane >> 4) * 8) * 2;
                ldsm4(ah[mf], ra);
                ldsm4(al[mf], ra + TILE_B);
            }
#pragma unroll
            for (int nf16 = 0; nf16 < 2; nf16++) {
                uint32_t rb = stage + 2 * TILE_B +
                    ((wn * 32 + nf16 * 16 + (lane & 7) + (((lane >> 4) & 1) << 3)) * LDSM_STRIDE +
                     s * 16 + ((lane >> 3) & 1) * 8) * 2;
                uint32_t t[4];
                ldsm4(t, rb);
                bh[nf16 * 2][0] = t[0]; bh[nf16 * 2][1] = t[1];
                bh[nf16 * 2 + 1][0] = t[2]; bh[nf16 * 2 + 1][1] = t[3];
                ldsm4(t, rb + TILE_B);
                bl[nf16 * 2][0] = t[0]; bl[nf16 * 2][1] = t[1];
                bl[nf16 * 2 + 1][0] = t[2]; bl[nf16 * 2 + 1][1] = t[3];
            }
#pragma unroll
            for (int mf = 0; mf < 4; mf++)
#pragma unroll
                for (int nf = 0; nf < 4; nf++) {
                    if (F16) {
                        mma_fp(acc[mf][nf], ah[mf], bh[nf]);
                        mma_fp(acc[mf][nf], al[mf], bl[nf]);
                    } else {
                        mma_bf(acc[mf][nf], ah[mf], bh[nf]);
                        mma_bf(acc[mf][nf], al[mf], bh[nf]);
                        mma_bf(acc[mf][nf], ah[mf], bl[nf]);
                    }
                }
        }
    }

    const int r0 = lane >> 2, c0 = (lane & 3) * 2;
    if (RC) {
        __shared__ int zc[BN];
        __syncthreads();
        if (tid < BN) zc[tid] = 0;
        __syncthreads();
        int cnt0[4] = {0, 0, 0, 0}, cnt1[4] = {0, 0, 0, 0};
#pragma unroll
        for (int mf = 0; mf < 4; mf++)
#pragma unroll
            for (int nf = 0; nf < 4; nf++) {
                float v0 = fmaxf(acc[mf][nf][0], 0.0f);
                float v1 = fmaxf(acc[mf][nf][1], 0.0f);
                float v2 = fmaxf(acc[mf][nf][2], 0.0f);
                float v3 = fmaxf(acc[mf][nf][3], 0.0f);
                cnt0[nf] += (v0 == 0.0f) + (v2 == 0.0f);
                cnt1[nf] += (v1 == 0.0f) + (v3 == 0.0f);
                int ra = bm + wm * 64 + mf * 16 + r0;
                int col = bn + wn * 32 + nf * 8 + c0;
                *(float2*)&C[(size_t)ra * N + col] = make_float2(v0, v1);
                *(float2*)&C[(size_t)(ra + 8) * N + col] = make_float2(v2, v3);
                const float sc = 0.0009765625f;   // 2^-10
                size_t pa = (size_t)ra * (N / 2) + (col >> 1);
                size_t pb = (size_t)(ra + 8) * (N / 2) + (col >> 1);
                ((uint32_t*)g_x2f)[pa]  = packh(__float2half(v0), __float2half(v1));
                ((uint32_t*)g_x2fs)[pa] = packh(__float2half(v0 * sc), __float2half(v1 * sc));
                ((uint32_t*)g_x2f)[pb]  = packh(__float2half(v2), __float2half(v3));
                ((uint32_t*)g_x2fs)[pb] = packh(__float2half(v2 * sc), __float2half(v3 * sc));
            }
#pragma unroll
        for (int nf = 0; nf < 4; nf++) {
            atomicAdd(&zc[wn * 32 + nf * 8 + c0], cnt0[nf]);
            atomicAdd(&zc[wn * 32 + nf * 8 + c0 + 1], cnt1[nf]);
        }
        __syncthreads();
        if (tid < BN) {
            int b = bm / SEQ;
            atomicAdd(&g_zero[b * INTER + bn + tid], zc[tid]);
        }
    } else {
#pragma unroll
        for (int mf = 0; mf < 4; mf++)
#pragma unroll
            for (int nf = 0; nf < 4; nf++) {
                int ra = bm + wm * 64 + mf * 16 + r0;
                int col = bn + wn * 32 + nf * 8 + c0;
                *(float2*)&C[(size_t)ra * N + col] = make_float2(acc[mf][nf][0], acc[mf][nf][1]);
                *(float2*)&C[(size_t)(ra + 8) * N + col] = make_float2(acc[mf][nf][2], acc[mf][nf][3]);
            }
    }
}

// ---------------- topk + gather ----------------
__global__ void topk_kernel() {
    const int b = blockIdx.x, tid = threadIdx.x;
    __shared__ unsigned red[256];
    __shared__ int chosen[KSEL];
    for (int sel = 0; sel < KSEL; sel++) {
        unsigned best = 0xFFFFFFFFu;
        for (int j = tid; j < INTER; j += 256) {
            bool skip = false;
            for (int c = 0; c < sel; c++) if (chosen[c] == j) skip = true;
            if (!skip) best = min(best, ((unsigned)g_zero[b * INTER + j] << 13) | (unsigned)j);
        }
        red[tid] = best;
        __syncthreads();
        for (int s = 128; s > 0; s >>= 1) {
            if (tid < s) red[tid] = min(red[tid], red[tid + s]);
            __syncthreads();
        }
        if (tid == 0) { chosen[sel] = (int)(red[0] & 8191u); g_topk[b * KSEL + sel] = chosen[sel]; }
        __syncthreads();
    }
}

__global__ void gather_kernel(float* __restrict__ out) {
    int idx = blockIdx.x * blockDim.x + threadIdx.x;
    if (idx >= NB * SEQ * KSEL) return;
    int i = idx % KSEL, row = idx / KSEL, b = row / SEQ;
    out[idx] = g_x2[(size_t)row * INTER + g_topk[b * KSEL + i]];
}

// ---------------- launch ----------------
extern "C" void kernel_launch(void* const* d_in, const int* in_sizes, int n_in,
                              void* d_out, int out_size)
{
    const float* x1 = (const float*)d_in[0];
    const float* w_up = (const float*)d_in[1];
    const float* w_up_la = (const float*)d_in[2];
    const float* w_up_lb = (const float*)d_in[3];
    const float* w_down = (const float*)d_in[4];
    const float* w_down_la = (const float*)d_in[5];
    const float* w_down_lb = (const float*)d_in[6];
    float* out = (float*)d_out;

    float* px2;
    __nv_bfloat16 *x1h, *x1l, *uh, *ul, *lth, *ltl, *ubh, *ubl;
    __half *x2f, *x2fs, *wdf, *wdls, *ltf, *ltfs, *dbf, *dbls;
    cudaGetSymbolAddress((void**)&px2, g_x2);
    cudaGetSymbolAddress((void**)&x1h, g_x1h);
    cudaGetSymbolAddress((void**)&x1l, g_x1l);
    cudaGetSymbolAddress((void**)&uh, g_wupT_h);
    cudaGetSymbolAddress((void**)&ul, g_wupT_l);
    cudaGetSymbolAddress((void**)&lth, g_lth);
    cudaGetSymbolAddress((void**)&ltl, g_ltl);
    cudaGetSymbolAddress((void**)&ubh, g_lubh);
    cudaGetSymbolAddress((void**)&ubl, g_lubl);
    cudaGetSymbolAddress((void**)&x2f, g_x2f);
    cudaGetSymbolAddress((void**)&x2fs, g_x2fs);
    cudaGetSymbolAddress((void**)&wdf, g_wdnT_f);
    cudaGetSymbolAddress((void**)&wdls, g_wdnT_ls);
    cudaGetSymbolAddress((void**)&ltf, g_ltf);
    cudaGetSymbolAddress((void**)&ltfs, g_ltfs);
    cudaGetSymbolAddress((void**)&dbf, g_ldbf);
    cudaGetSymbolAddress((void**)&dbls, g_ldbls);

    cudaFuncSetAttribute((const void*)mma_gemm<true, false>,
                         cudaFuncAttributeMaxDynamicSharedMemorySize, DYN_SMEM);
    cudaFuncSetAttribute((const void*)mma_gemm<false, true>,
                         cudaFuncAttributeMaxDynamicSharedMemorySize, DYN_SMEM);

    // 1: w_up transpose + bf16 split
    transpose_split_bf<<<dim3(INTER / 32, HID / 32), 256>>>(w_up, uh, ul, HID, INTER);
    // 2: fused elementwise prep (x1 split, lora_b up, zinit, w_down f16 transpose, lora_b down)
    prep_fused<<<PREP_GRID, 256>>>(x1, w_up_lb, w_down, w_down_lb);
    // 3: t_up = x1 @ w_up_lora_a  -> padded bf16 split
    rank16_direct<false><<<MTOT / 32, 256>>>(x1, w_up_la, HID);
    // 4: up GEMM (bf16 3-term) + relu + counts + x2 (fp32, f16, f16-scaled)
    mma_gemm<true, false><<<dim3(INTER / BN, MTOT / BM), 256, DYN_SMEM>>>(
        x1h, x1l, uh, ul, lth, ltl, ubh, ubl, px2, INTER, HID);
    // 5: t_down = x2 @ w_down_lora_a -> padded f16 pair
    rank16_direct<true><<<MTOT / 32, 256>>>(px2, w_down_la, INTER);
    // 6: down GEMM (fp16 2-term)
    mma_gemm<false, true><<<dim3(HID / BN, MTOT / BM), 256, DYN_SMEM>>>(
        (const __nv_bfloat16*)x2f, (const __nv_bfloat16*)x2fs,
        (const __nv_bfloat16*)wdf, (const __nv_bfloat16*)wdls,
        (const __nv_bfloat16*)ltf, (const __nv_bfloat16*)ltfs,
        (const __nv_bfloat16*)dbf, (const __nv_bfloat16*)dbls,
        out, HID, INTER);
    // 7/8: top-k + gather
    topk_kernel<<<NB, 256>>>();
    gather_kernel<<<(NB * SEQ * KSEL + 255) / 256, 256>>>(out + (size_t)MTOT * HID);
}

// round 8
// speedup vs baseline: 2.7593x; 1.1890x over previous
#include <cuda_runtime.h>
#include <cuda_bf16.h>
#include <cuda_fp16.h>
#include <cstdint>

#define HID 2048
#define INTER 8192
#define RANK 16
#define SEQ 2048
#define NB 4
#define MTOT 8192
#define KSEL 10

#define BM 128
#define BN 128
#define BK 32
#define LDSM_STRIDE 40
#define TILE_B (128 * LDSM_STRIDE * 2)
#define STAGE_B (4 * TILE_B)
#define NSTAGE 2
#define DYN_SMEM (NSTAGE * STAGE_B)   // 81920

// ---------------- device scratch ----------------
__device__ float g_x2[(size_t)MTOT * INTER];
__device__ __half g_x2f[(size_t)MTOT * INTER];
__device__ __half g_x2fs[(size_t)MTOT * INTER];
__device__ __nv_bfloat16 g_x1h[(size_t)MTOT * HID];
__device__ __nv_bfloat16 g_x1l[(size_t)MTOT * HID];
__device__ __nv_bfloat16 g_wupT_h[(size_t)INTER * HID];
__device__ __nv_bfloat16 g_wupT_l[(size_t)INTER * HID];
__device__ __half g_wdnT_f[(size_t)HID * INTER];
__device__ __half g_wdnT_ls[(size_t)HID * INTER];
__device__ float g_tup[MTOT * RANK];
__device__ float g_tdn[MTOT * RANK];
__device__ __nv_bfloat16 g_lth[MTOT * 32];
__device__ __nv_bfloat16 g_ltl[MTOT * 32];
__device__ __half g_ltf[MTOT * 32];
__device__ __half g_ltfs[MTOT * 32];
__device__ __nv_bfloat16 g_lubh[INTER * 32];
__device__ __nv_bfloat16 g_lubl[INTER * 32];
__device__ __half g_ldbf[HID * 32];
__device__ __half g_ldbls[HID * 32];
__device__ int g_zero[NB * INTER];
__device__ int g_topk[NB * KSEL];

// ---------------- helpers ----------------
__device__ __forceinline__ uint32_t smem_u32(const void* p) {
    uint32_t a;
    asm("{ .reg .u64 t; cvta.to.shared.u64 t, %1; cvt.u32.u64 %0, t; }" : "=r"(a) : "l"(p));
    return a;
}
__device__ __forceinline__ void split1(float x, __nv_bfloat16& h, __nv_bfloat16& l) {
    h = __float2bfloat16(x);
    l = __float2bfloat16(x - __bfloat162float(h));
}
__device__ __forceinline__ void split1f(float x, __half& h, __half& ls) {
    h = __float2half(x);
    ls = __float2half((x - __half2float(h)) * 1024.0f);
}
__device__ __forceinline__ uint32_t packbf(__nv_bfloat16 a, __nv_bfloat16 b) {
    __nv_bfloat162 t = __halves2bfloat162(a, b);
    return *reinterpret_cast<uint32_t*>(&t);
}
__device__ __forceinline__ uint32_t packh(__half a, __half b) {
    __half2 t = __halves2half2(a, b);
    return *reinterpret_cast<uint32_t*>(&t);
}
__device__ __forceinline__ void cpasync16(uint32_t dst, const void* src) {
    asm volatile("cp.async.cg.shared.global [%0], [%1], 16;" :: "r"(dst), "l"(src));
}
__device__ __forceinline__ void ldsm4(uint32_t (&r)[4], uint32_t addr) {
    asm volatile("ldmatrix.sync.aligned.m8n8.x4.shared.b16 {%0,%1,%2,%3}, [%4];"
                 : "=r"(r[0]), "=r"(r[1]), "=r"(r[2]), "=r"(r[3]) : "r"(addr));
}
__device__ __forceinline__ void mma_bf(float (&d)[4], const uint32_t (&a)[4], const uint32_t* b) {
    asm volatile("mma.sync.aligned.m16n8k16.row.col.f32.bf16.bf16.f32 "
                 "{%0,%1,%2,%3},{%4,%5,%6,%7},{%8,%9},{%0,%1,%2,%3};"
                 : "+f"(d[0]), "+f"(d[1]), "+f"(d[2]), "+f"(d[3])
                 : "r"(a[0]), "r"(a[1]), "r"(a[2]), "r"(a[3]), "r"(b[0]), "r"(b[1]));
}
__device__ __forceinline__ void mma_fp(float (&d)[4], const uint32_t (&a)[4], const uint32_t* b) {
    asm volatile("mma.sync.aligned.m16n8k16.row.col.f32.f16.f16.f32 "
                 "{%0,%1,%2,%3},{%4,%5,%6,%7},{%8,%9},{%0,%1,%2,%3};"
                 : "+f"(d[0]), "+f"(d[1]), "+f"(d[2]), "+f"(d[3])
                 : "r"(a[0]), "r"(a[1]), "r"(a[2]), "r"(a[3]), "r"(b[0]), "r"(b[1]));
}

// ---------------- w_up transpose + bf16 split ----------------
__global__ __launch_bounds__(256) void transpose_split_bf(
    const float* __restrict__ W, __nv_bfloat16* __restrict__ hiT,
    __nv_bfloat16* __restrict__ loT, int R, int C)
{
    __shared__ float t[32][33];
    const int tx = threadIdx.x & 31, ty = threadIdx.x >> 5;
    const int r0 = blockIdx.y * 32, c0 = blockIdx.x * 32;
#pragma unroll
    for (int i = 0; i < 4; i++) {
        int r = ty + i * 8;
        t[r][tx] = W[(size_t)(r0 + r) * C + c0 + tx];
    }
    __syncthreads();
#pragma unroll
    for (int i = 0; i < 4; i++) {
        int c = ty + i * 8;
        __nv_bfloat16 h, l;
        split1(t[tx][c], h, l);
        hiT[(size_t)(c0 + c) * R + r0 + tx] = h;
        loT[(size_t)(c0 + c) * R + r0 + tx] = l;
    }
}

// ---------------- fused elementwise prep ----------------
#define PREP_T0 16384                 // x1 split
#define PREP_T1 (PREP_T0 + 1024)     // lora_b up
#define PREP_T2 (PREP_T1 + 128)      // zero g_zero
#define PREP_T3 (PREP_T2 + 16384)    // w_down transpose + f16 split
#define PREP_T4 (PREP_T3 + 256)      // lora_b down
#define PREP_T5 (PREP_T4 + 128)      // zero g_tup (float4)
#define PREP_GRID (PREP_T5 + 128)    // zero g_tdn
__global__ __launch_bounds__(256) void prep_fused(
    const float* __restrict__ x1, const float* __restrict__ w_up_lb,
    const float* __restrict__ w_down, const float* __restrict__ w_down_lb)
{
    __shared__ float t[32][33];
    const int bid = blockIdx.x, tid = threadIdx.x;
    if (bid < PREP_T0) {
        size_t i = (size_t)bid * 256 + tid;
        float4 v = *(const float4*)(x1 + i * 4);
        __nv_bfloat16 h0, h1, h2, h3, l0, l1, l2, l3;
        split1(v.x, h0, l0); split1(v.y, h1, l1);
        split1(v.z, h2, l2); split1(v.w, h3, l3);
        ((uint2*)g_x1h)[i] = make_uint2(packbf(h0, h1), packbf(h2, h3));
        ((uint2*)g_x1l)[i] = make_uint2(packbf(l0, l1), packbf(l2, l3));
    } else if (bid < PREP_T1) {
        int i = (bid - PREP_T0) * 256 + tid;
        int n = i >> 5, j = i & 31;
        float v = (j < 16) ? w_up_lb[(size_t)j * INTER + n] : 0.0f;
        __nv_bfloat16 h, l;
        split1(v, h, l);
        g_lubh[i] = h; g_lubl[i] = l;
    } else if (bid < PREP_T2) {
        int i = (bid - PREP_T1) * 256 + tid;
        if (i < NB * INTER) g_zero[i] = 0;
    } else if (bid < PREP_T3) {
        int tb = bid - PREP_T2;
        int bx = tb & 63, by = tb >> 6;
        const int tx = tid & 31, ty = tid >> 5;
        const int r0 = by * 32, c0 = bx * 32;
#pragma unroll
        for (int i = 0; i < 4; i++) {
            int r = ty + i * 8;
            t[r][tx] = w_down[(size_t)(r0 + r) * HID + c0 + tx];
        }
        __syncthreads();
#pragma unroll
        for (int i = 0; i < 4; i++) {
            int c = ty + i * 8;
            __half h, ls;
            split1f(t[tx][c], h, ls);
            g_wdnT_f[(size_t)(c0 + c) * INTER + r0 + tx] = h;
            g_wdnT_ls[(size_t)(c0 + c) * INTER + r0 + tx] = ls;
        }
    } else if (bid < PREP_T4) {
        int i = (bid - PREP_T3) * 256 + tid;
        int n = i >> 5, j = i & 31;
        float v = (j < 16) ? w_down_lb[(size_t)j * HID + n] : 0.0f;
        __half h, ls;
        split1f(v, h, ls);
        g_ldbf[i] = h; g_ldbls[i] = ls;
    } else if (bid < PREP_T5) {
        int i = (bid - PREP_T4) * 256 + tid;
        ((float4*)g_tup)[i] = make_float4(0.f, 0.f, 0.f, 0.f);
    } else {
        int i = (bid - PREP_T5) * 256 + tid;
        ((float4*)g_tdn)[i] = make_float4(0.f, 0.f, 0.f, 0.f);
    }
}

// ---------------- rank-16 GEMM, K-split partial with atomic accumulate ------
__global__ __launch_bounds__(256) void rank16_partial(
    const float* __restrict__ X, const float* __restrict__ A16,
    float* __restrict__ T, int K, int kchunk)
{
    const int wid = threadIdx.x >> 5, lane = threadIdx.x & 31;
    const int row0 = (blockIdx.x * 8 + wid) * 4;
    const int kbase = blockIdx.y * kchunk;
    float acc[4][16];
#pragma unroll
    for (int r = 0; r < 4; r++)
#pragma unroll
        for (int j = 0; j < 16; j++) acc[r][j] = 0.0f;
    for (int k0 = kbase + lane * 4; k0 < kbase + kchunk; k0 += 128) {
        float4 xv[4];
#pragma unroll
        for (int r = 0; r < 4; r++) xv[r] = *(const float4*)(X + (size_t)(row0 + r) * K + k0);
#pragma unroll
        for (int e = 0; e < 4; e++) {
            const float* Ar = A16 + (size_t)(k0 + e) * 16;
            float av[16];
#pragma unroll
            for (int j = 0; j < 16; j += 4) {
                float4 a = *(const float4*)(Ar + j);
                av[j] = a.x; av[j + 1] = a.y; av[j + 2] = a.z; av[j + 3] = a.w;
            }
#pragma unroll
            for (int r = 0; r < 4; r++) {
                float xs = (e == 0) ? xv[r].x : (e == 1) ? xv[r].y : (e == 2) ? xv[r].z : xv[r].w;
#pragma unroll
                for (int j = 0; j < 16; j++) acc[r][j] = fmaf(xs, av[j], acc[r][j]);
            }
        }
    }
#pragma unroll
    for (int r = 0; r < 4; r++)
#pragma unroll
        for (int j = 0; j < 16; j++)
#pragma unroll
            for (int o = 16; o > 0; o >>= 1)
                acc[r][j] += __shfl_xor_sync(0xffffffffu, acc[r][j], o);
    if (lane < 4) {
        int r = lane;
#pragma unroll
        for (int j = 0; j < 16; j++)
            atomicAdd(&T[(size_t)(row0 + r) * 16 + j], acc[r][j]);
    }
}

// finalize: fp32 T[M][16] -> padded split [M][32]
template <bool F16OUT>
__global__ void lora_finalize(const float* __restrict__ T) {
    int i = blockIdx.x * blockDim.x + threadIdx.x;   // MTOT*32
    if (i >= MTOT * 32) return;
    int j = i & 31;
    float v = (j < 16) ? T[(i >> 5) * 16 + j] : 0.0f;
    if (F16OUT) {
        g_ltf[i] = __float2half(v);
        g_ltfs[i] = __float2half(v * 0.0009765625f);
    } else {
        __nv_bfloat16 h, l;
        split1(v, h, l);
        g_lth[i] = h; g_ltl[i] = l;
    }
}

// ---------------- main mma.sync GEMM (2 CTAs/SM, 2-stage) ----------------
template <bool RC, bool F16>
__global__ __launch_bounds__(256, 2) void mma_gemm(
    const __nv_bfloat16* __restrict__ A0, const __nv_bfloat16* __restrict__ A1,
    const __nv_bfloat16* __restrict__ B0, const __nv_bfloat16* __restrict__ B1,
    const __nv_bfloat16* __restrict__ lt0, const __nv_bfloat16* __restrict__ lt1,
    const __nv_bfloat16* __restrict__ lb0, const __nv_bfloat16* __restrict__ lb1,
    float* __restrict__ C, int N, int K)
{
    extern __shared__ char smem[];
    const uint32_t sbase = smem_u32(smem);
    const int tid = threadIdx.x, lane = tid & 31, wid = tid >> 5;
    const int wm = wid >> 2, wn = wid & 3;
    const int bm = blockIdx.y * BM, bn = blockIdx.x * BN;
    const int nmain = K / BK, ntot = nmain + 1;

    auto issue = [&](int c) {
        const __nv_bfloat16 *pa0, *pa1, *pb0, *pb1;
        int sa, sb;
        if (c < nmain) {
            size_t ao = (size_t)bm * K + c * BK, bo = (size_t)bn * K + c * BK;
            pa0 = A0 + ao; pa1 = A1 + ao; sa = K;
            pb0 = B0 + bo; pb1 = B1 + bo; sb = K;
        } else {
            pa0 = lt0 + (size_t)bm * 32; pa1 = lt1 + (size_t)bm * 32; sa = 32;
            pb0 = lb0 + (size_t)bn * 32; pb1 = lb1 + (size_t)bn * 32; sb = 32;
        }
        uint32_t stage = sbase + (c & 1) * STAGE_B;
#pragma unroll
        for (int q = 0; q < 8; q++) {
            int qi = tid + q * 256;
            int arr = qi >> 9, idx = qi & 511;
            int r = idx >> 2, cc = idx & 3;
            const __nv_bfloat16* src;
            if (arr == 0)      src = pa0 + (size_t)r * sa + cc * 8;
            else if (arr == 1) src = pa1 + (size_t)r * sa + cc * 8;
            else if (arr == 2) src = pb0 + (size_t)r * sb + cc * 8;
            else               src = pb1 + (size_t)r * sb + cc * 8;
            cpasync16(stage + arr * TILE_B + r * (LDSM_STRIDE * 2) + cc * 16, src);
        }
        asm volatile("cp.async.commit_group;");
    };

    issue(0);

    float acc[4][4][4];
#pragma unroll
    for (int mf = 0; mf < 4; mf++)
#pragma unroll
        for (int nf = 0; nf < 4; nf++)
#pragma unroll
            for (int q = 0; q < 4; q++) acc[mf][nf][q] = 0.0f;

    for (int c = 0; c < ntot; c++) {
        if (c + 1 < ntot) {
            issue(c + 1);
            asm volatile("cp.async.wait_group 1;" ::: "memory");
        } else {
            asm volatile("cp.async.wait_group 0;" ::: "memory");
        }
        __syncthreads();
        const uint32_t stage = sbase + (c & 1) * STAGE_B;
#pragma unroll
        for (int s = 0; s < 2; s++) {
            uint32_t ah[4][4], al[4][4], bh[4][2], bl[4][2];
#pragma unroll
            for (int mf = 0; mf < 4; mf++) {
                uint32_t ra = stage +
                    ((wm * 64 + mf * 16 + (lane & 15)) * LDSM_STRIDE +
                     s * 16 + (lane >> 4) * 8) * 2;
                ldsm4(ah[mf], ra);
                ldsm4(al[mf], ra + TILE_B);
            }
#pragma unroll
            for (int nf16 = 0; nf16 < 2; nf16++) {
                uint32_t rb = stage + 2 * TILE_B +
                    ((wn * 32 + nf16 * 16 + (lane & 7) + (((lane >> 4) & 1) << 3)) * LDSM_STRIDE +
                     s * 16 + ((lane >> 3) & 1) * 8) * 2;
                uint32_t t[4];
                ldsm4(t, rb);
                bh[nf16 * 2][0] = t[0]; bh[nf16 * 2][1] = t[1];
                bh[nf16 * 2 + 1][0] = t[2]; bh[nf16 * 2 + 1][1] = t[3];
                ldsm4(t, rb + TILE_B);
                bl[nf16 * 2][0] = t[0]; bl[nf16 * 2][1] = t[1];
                bl[nf16 * 2 + 1][0] = t[2]; bl[nf16 * 2 + 1][1] = t[3];
            }
#pragma unroll
            for (int mf = 0; mf < 4; mf++)
#pragma unroll
                for (int nf = 0; nf < 4; nf++) {
                    if (F16) {
                        mma_fp(acc[mf][nf], ah[mf], bh[nf]);
                        mma_fp(acc[mf][nf], al[mf], bl[nf]);
                    } else {
                        mma_bf(acc[mf][nf], ah[mf], bh[nf]);
                        mma_bf(acc[mf][nf], al[mf], bh[nf]);
                        mma_bf(acc[mf][nf], ah[mf], bl[nf]);
                    }
                }
        }
        __syncthreads();
    }

    const int r0 = lane >> 2, c0 = (lane & 3) * 2;
    if (RC) {
        __shared__ int zc[BN];
        if (tid < BN) zc[tid] = 0;
        __syncthreads();
        int cnt0[4] = {0, 0, 0, 0}, cnt1[4] = {0, 0, 0, 0};
#pragma unroll
        for (int mf = 0; mf < 4; mf++)
#pragma unroll
            for (int nf = 0; nf < 4; nf++) {
                float v0 = fmaxf(acc[mf][nf][0], 0.0f);
                float v1 = fmaxf(acc[mf][nf][1], 0.0f);
                float v2 = fmaxf(acc[mf][nf][2], 0.0f);
                float v3 = fmaxf(acc[mf][nf][3], 0.0f);
                cnt0[nf] += (v0 == 0.0f) + (v2 == 0.0f);
                cnt1[nf] += (v1 == 0.0f) + (v3 == 0.0f);
                int ra = bm + wm * 64 + mf * 16 + r0;
                int col = bn + wn * 32 + nf * 8 + c0;
                *(float2*)&C[(size_t)ra * N + col] = make_float2(v0, v1);
                *(float2*)&C[(size_t)(ra + 8) * N + col] = make_float2(v2, v3);
                const float sc = 0.0009765625f;
                size_t pa = (size_t)ra * (N / 2) + (col >> 1);
                size_t pb = (size_t)(ra + 8) * (N / 2) + (col >> 1);
                ((uint32_t*)g_x2f)[pa]  = packh(__float2half(v0), __float2half(v1));
                ((uint32_t*)g_x2fs)[pa] = packh(__float2half(v0 * sc), __float2half(v1 * sc));
                ((uint32_t*)g_x2f)[pb]  = packh(__float2half(v2), __float2half(v3));
                ((uint32_t*)g_x2fs)[pb] = packh(__float2half(v2 * sc), __float2half(v3 * sc));
            }
#pragma unroll
        for (int nf = 0; nf < 4; nf++) {
            atomicAdd(&zc[wn * 32 + nf * 8 + c0], cnt0[nf]);
            atomicAdd(&zc[wn * 32 + nf * 8 + c0 + 1], cnt1[nf]);
        }
        __syncthreads();
        if (tid < BN) {
            int b = bm / SEQ;
            atomicAdd(&g_zero[b * INTER + bn + tid], zc[tid]);
        }
    } else {
#pragma unroll
        for (int mf = 0; mf < 4; mf++)
#pragma unroll
            for (int nf = 0; nf < 4; nf++) {
                int ra = bm + wm * 64 + mf * 16 + r0;
                int col = bn + wn * 32 + nf * 8 + c0;
                *(float2*)&C[(size_t)ra * N + col] = make_float2(acc[mf][nf][0], acc[mf][nf][1]);
                *(float2*)&C[(size_t)(ra + 8) * N + col] = make_float2(acc[mf][nf][2], acc[mf][nf][3]);
            }
    }
}

// ---------------- topk + gather ----------------
__global__ void topk_kernel() {
    const int b = blockIdx.x, tid = threadIdx.x;
    __shared__ unsigned red[256];
    __shared__ int chosen[KSEL];
    for (int sel = 0; sel < KSEL; sel++) {
        unsigned best = 0xFFFFFFFFu;
        for (int j = tid; j < INTER; j += 256) {
            bool skip = false;
            for (int c = 0; c < sel; c++) if (chosen[c] == j) skip = true;
            if (!skip) best = min(best, ((unsigned)g_zero[b * INTER + j] << 13) | (unsigned)j);
        }
        red[tid] = best;
        __syncthreads();
        for (int s = 128; s > 0; s >>= 1) {
            if (tid < s) red[tid] = min(red[tid], red[tid + s]);
            __syncthreads();
        }
        if (tid == 0) { chosen[sel] = (int)(red[0] & 8191u); g_topk[b * KSEL + sel] = chosen[sel]; }
        __syncthreads();
    }
}

__global__ void gather_kernel(float* __restrict__ out) {
    int idx = blockIdx.x * blockDim.x + threadIdx.x;
    if (idx >= NB * SEQ * KSEL) return;
    int i = idx % KSEL, row = idx / KSEL, b = row / SEQ;
    out[idx] = g_x2[(size_t)row * INTER + g_topk[b * KSEL + i]];
}

// ---------------- launch ----------------
extern "C" void kernel_launch(void* const* d_in, const int* in_sizes, int n_in,
                              void* d_out, int out_size)
{
    const float* x1 = (const float*)d_in[0];
    const float* w_up = (const float*)d_in[1];
    const float* w_up_la = (const float*)d_in[2];
    const float* w_up_lb = (const float*)d_in[3];
    const float* w_down = (const float*)d_in[4];
    const float* w_down_la = (const float*)d_in[5];
    const float* w_down_lb = (const float*)d_in[6];
    float* out = (float*)d_out;

    float *px2, *ptup, *ptdn;
    __nv_bfloat16 *x1h, *x1l, *uh, *ul, *lth, *ltl, *ubh, *ubl;
    __half *x2f, *x2fs, *wdf, *wdls, *ltf, *ltfs, *dbf, *dbls;
    cudaGetSymbolAddress((void**)&px2, g_x2);
    cudaGetSymbolAddress((void**)&ptup, g_tup);
    cudaGetSymbolAddress((void**)&ptdn, g_tdn);
    cudaGetSymbolAddress((void**)&x1h, g_x1h);
    cudaGetSymbolAddress((void**)&x1l, g_x1l);
    cudaGetSymbolAddress((void**)&uh, g_wupT_h);
    cudaGetSymbolAddress((void**)&ul, g_wupT_l);
    cudaGetSymbolAddress((void**)&lth, g_lth);
    cudaGetSymbolAddress((void**)&ltl, g_ltl);
    cudaGetSymbolAddress((void**)&ubh, g_lubh);
    cudaGetSymbolAddress((void**)&ubl, g_lubl);
    cudaGetSymbolAddress((void**)&x2f, g_x2f);
    cudaGetSymbolAddress((void**)&x2fs, g_x2fs);
    cudaGetSymbolAddress((void**)&wdf, g_wdnT_f);
    cudaGetSymbolAddress((void**)&wdls, g_wdnT_ls);
    cudaGetSymbolAddress((void**)&ltf, g_ltf);
    cudaGetSymbolAddress((void**)&ltfs, g_ltfs);
    cudaGetSymbolAddress((void**)&dbf, g_ldbf);
    cudaGetSymbolAddress((void**)&dbls, g_ldbls);

    cudaFuncSetAttribute((const void*)mma_gemm<true, false>,
                         cudaFuncAttributeMaxDynamicSharedMemorySize, DYN_SMEM);
    cudaFuncSetAttribute((const void*)mma_gemm<false, true>,
                         cudaFuncAttributeMaxDynamicSharedMemorySize, DYN_SMEM);

    transpose_split_bf<<<dim3(INTER / 32, HID / 32), 256>>>(w_up, uh, ul, HID, INTER);
    prep_fused<<<PREP_GRID, 256>>>(x1, w_up_lb, w_down, w_down_lb);

    // t_up = x1 @ w_up_lora_a (K-split x4)
    rank16_partial<<<dim3(MTOT / 32, 4), 256>>>(x1, w_up_la, ptup, HID, HID / 4);
    lora_finalize<false><<<(MTOT * 32 + 255) / 256, 256>>>(ptup);

    // up GEMM (bf16 3-term) + relu + counts + x2 (fp32 + f16 pair)
    mma_gemm<true, false><<<dim3(INTER / BN, MTOT / BM), 256, DYN_SMEM>>>(
        x1h, x1l, uh, ul, lth, ltl, ubh, ubl, px2, INTER, HID);

    // t_down = x2 @ w_down_lora_a (K-split x8)
    rank16_partial<<<dim3(MTOT / 32, 8), 256>>>(px2, w_down_la, ptdn, INTER, INTER / 8);
    lora_finalize<true><<<(MTOT * 32 + 255) / 256, 256>>>(ptdn);

    // down GEMM (fp16 2-term)
    mma_gemm<false, true><<<dim3(HID / BN, MTOT / BM), 256, DYN_SMEM>>>(
        (const __nv_bfloat16*)x2f, (const __nv_bfloat16*)x2fs,
        (const __nv_bfloat16*)wdf, (const __nv_bfloat16*)wdls,
        (const __nv_bfloat16*)ltf, (const __nv_bfloat16*)ltfs,
        (const __nv_bfloat16*)dbf, (const __nv_bfloat16*)dbls,
        out, HID, INTER);

    topk_kernel<<<NB, 256>>>();
    gather_kernel<<<(NB * SEQ * KSEL + 255) / 256, 256>>>(out + (size_t)MTOT * HID);
}